// round 15
// baseline (speedup 1.0000x reference)
#include <cuda_runtime.h>
#include <cuda_fp16.h>
#include <math.h>
#include <stdint.h>

// ---------------------------------------------------------------------------
// Shapes (fixed): x [4,2048,2048] -> T=8192, d=2048 ; base_W [2048,2048];
// base_b [2048]; A [16,16,2048]; B [16,2048,16]; gate_v [16,2048];
// alphas[16]; top_k=2
// ---------------------------------------------------------------------------

#define D_IN   2048
#define D_OUT  2048
#define N_EXP  16
#define RANK   16
#define T_MAX  8192
#define EPSV   1e-6f
#define KLORA  (N_EXP * RANK)           // 256

// Scratch (static device memory -- no allocation)
__device__ int   g_idx[T_MAX * 2];
__device__ float g_w[T_MAX * 2];

// fp16 operands
__device__ __half g_Xh[(size_t)T_MAX * D_IN];
__device__ __half g_Wh[(size_t)D_OUT * D_IN];
__device__ __half g_Ah[(size_t)KLORA * D_IN];
__device__ __half g_Mw[(size_t)T_MAX * KLORA];    // weighted mid (fp16)
__device__ __half g_Bh[(size_t)D_OUT * KLORA];    // Bflat[o, e*16+r]

// ---------------------------------------------------------------------------
// PTX helpers
// ---------------------------------------------------------------------------
__device__ __forceinline__ uint32_t smem_u32(const void* p) {
    uint32_t a;
    asm("{ .reg .u64 t; cvta.to.shared.u64 t, %1; cvt.u32.u64 %0, t; }"
        : "=r"(a) : "l"(p));
    return a;
}
__device__ __forceinline__ void cp16(uint32_t dst, const void* src) {
    asm volatile("cp.async.cg.shared.global [%0], [%1], 16;" :: "r"(dst), "l"(src));
}
__device__ __forceinline__ void ldsm_x4(uint32_t* r, uint32_t addr) {
    asm volatile("ldmatrix.sync.aligned.m8n8.x4.shared.b16 {%0,%1,%2,%3}, [%4];"
                 : "=r"(r[0]), "=r"(r[1]), "=r"(r[2]), "=r"(r[3]) : "r"(addr));
}
#define MMA16816(cd, af, b0, b1)                                              \
    asm volatile("mma.sync.aligned.m16n8k16.row.col.f32.f16.f16.f32 "        \
                 "{%0,%1,%2,%3}, {%4,%5,%6,%7}, {%8,%9}, {%0,%1,%2,%3};"      \
                 : "+f"((cd)[0]), "+f"((cd)[1]), "+f"((cd)[2]), "+f"((cd)[3]) \
                 : "r"((af)[0]), "r"((af)[1]), "r"((af)[2]), "r"((af)[3]),    \
                   "r"(b0), "r"(b1))

__device__ __forceinline__ uint32_t swz_off(int row, int chunk) {
    int s = (row & 3) ^ ((row >> 2) & 1);
    return (uint32_t)(row * 64 + ((chunk ^ s) << 4));
}

// ---------------------------------------------------------------------------
// Kernel 1 (s1): fused weight prep. Grid partitioned:
//   blocks [0, 4096)        : W fp32 -> Wh fp16       (1M float4)
//   blocks [4096, 4608)     : A fp32 -> Ah fp16       (128K float4)
//   blocks [4608, 4736)     : B [E,d_out,r] -> Bh [d_out, E*r] fp16
// ---------------------------------------------------------------------------
#define PREP_W_BLOCKS (D_OUT * D_IN / 4 / 256)          // 4096
#define PREP_A_BLOCKS (KLORA * D_IN / 4 / 256)          // 512
#define PREP_B_BLOCKS (D_OUT * N_EXP / 256)             // 128
#define PREP_BLOCKS   (PREP_W_BLOCKS + PREP_A_BLOCKS + PREP_B_BLOCKS)

__global__ void __launch_bounds__(256)
prep_kernel(const float* __restrict__ Wm, const float* __restrict__ A,
            const float* __restrict__ B) {
    int b = blockIdx.x;
    if (b < PREP_W_BLOCKS + PREP_A_BLOCKS) {
        const float* src;
        __half* dst;
        int i;
        if (b < PREP_W_BLOCKS) {
            src = Wm; dst = g_Wh; i = b * 256 + threadIdx.x;
        } else {
            src = A; dst = g_Ah; i = (b - PREP_W_BLOCKS) * 256 + threadIdx.x;
        }
        float4 v = ((const float4*)src)[i];
        __half2* dp = (__half2*)dst;
        dp[2 * i + 0] = __half2(__float2half(v.x), __float2half(v.y));
        dp[2 * i + 1] = __half2(__float2half(v.z), __float2half(v.w));
    } else {
        int gidx = (b - PREP_W_BLOCKS - PREP_A_BLOCKS) * 256 + threadIdx.x;
        int o = gidx >> 4;
        int e = gidx & 15;
        const float4* src = (const float4*)(B + ((size_t)e * D_OUT + o) * RANK);
        __half2 buf[8];
#pragma unroll
        for (int q = 0; q < 4; q++) {
            float4 v = src[q];
            buf[q * 2 + 0] = __half2(__float2half(v.x), __float2half(v.y));
            buf[q * 2 + 1] = __half2(__float2half(v.z), __float2half(v.w));
        }
        uint4* dst = (uint4*)(g_Bh + (size_t)o * KLORA + e * RANK);
        dst[0] = ((uint4*)buf)[0];
        dst[1] = ((uint4*)buf)[1];
    }
}

// ---------------------------------------------------------------------------
// Kernel 2 (s0): convx = X fp32->fp16 + xnorm + routing dots + gnorm (free,
// from in-register gv) + per-token top-2 softmax. All fp32 exact paths.
// 512 threads, 16 tokens/block.
// ---------------------------------------------------------------------------
#define CONVX_TOKENS 16
#define CONVX_SMEM (CONVX_TOKENS * D_IN * 4)   // 128KB dynamic

__global__ void __launch_bounds__(512)
convx_kernel(const float* __restrict__ x, const float* __restrict__ gv,
             const float* __restrict__ alphas) {
    extern __shared__ float xs[];
    __shared__ float sdots[CONVX_TOKENS][N_EXP];
    __shared__ float sgn[N_EXP];
    __shared__ float sxn[CONVX_TOKENS];

    const int t0 = blockIdx.x * CONVX_TOKENS;
    const int w = threadIdx.x >> 5;
    const int l = threadIdx.x & 31;
    const int tid = threadIdx.x;

    // stage: warp w -> token t0+w (copy to smem, fp16 convert, xnorm)
    {
        const float4* xr = (const float4*)(x + (size_t)(t0 + w) * D_IN);
        float4* xsr = (float4*)(xs + (size_t)w * D_IN);
        __half2* hp = (__half2*)(g_Xh + (size_t)(t0 + w) * D_IN);
        float xx = 0.f;
#pragma unroll
        for (int i = 0; i < 16; i++) {
            int j = l + 32 * i;
            float4 v = xr[j];
            xsr[j] = v;
            xx += v.x * v.x + v.y * v.y + v.z * v.z + v.w * v.w;
            hp[j * 2 + 0] = __half2(__float2half(v.x), __float2half(v.y));
            hp[j * 2 + 1] = __half2(__float2half(v.z), __float2half(v.w));
        }
#pragma unroll
        for (int off = 16; off > 0; off >>= 1)
            xx += __shfl_down_sync(0xFFFFFFFFu, xx, off);
        if (l == 0) sxn[w] = sqrtf(xx) + EPSV;
    }
    __syncthreads();

    // warp w = expert w: gv row into registers; gnorm from the same registers
    float gvr[64];
    {
        const float* gvrow = gv + (size_t)w * D_IN;
#pragma unroll
        for (int i = 0; i < 64; i++) gvr[i] = gvrow[l + 32 * i];
        float gg = 0.f;
#pragma unroll
        for (int i = 0; i < 64; i++) gg += gvr[i] * gvr[i];
#pragma unroll
        for (int off = 16; off > 0; off >>= 1)
            gg += __shfl_down_sync(0xFFFFFFFFu, gg, off);
        if (l == 0) sgn[w] = sqrtf(gg) + EPSV;
    }

    // dots
#pragma unroll 1
    for (int t = 0; t < CONVX_TOKENS; t++) {
        const float* xt = xs + (size_t)t * D_IN;
        float s = 0.f;
#pragma unroll
        for (int i = 0; i < 64; i++) s += xt[l + 32 * i] * gvr[i];
#pragma unroll
        for (int off = 16; off > 0; off >>= 1)
            s += __shfl_down_sync(0xFFFFFFFFu, s, off);
        if (l == 0) sdots[t][w] = s;
    }
    __syncthreads();

    // top-2 + softmax (threads 0..15 -> one token each)
    if (tid < CONVX_TOKENS) {
        int t = t0 + tid;
        float inv = 1.f / (sxn[tid] * sqrtf((float)D_IN));
        float sc[N_EXP];
#pragma unroll
        for (int e = 0; e < N_EXP; e++)
            sc[e] = sdots[tid][e] * inv / sgn[e];

        int i0 = 0;
#pragma unroll
        for (int e = 1; e < N_EXP; e++) if (sc[e] > sc[i0]) i0 = e;
        int i1 = (i0 == 0) ? 1 : 0;
#pragma unroll
        for (int e = 0; e < N_EXP; e++)
            if (e != i0 && sc[e] > sc[i1]) i1 = e;

        float e1 = expf(sc[i1] - sc[i0]);
        float denom = 1.f + e1;
        g_idx[t * 2 + 0] = i0;
        g_idx[t * 2 + 1] = i1;
        g_w[t * 2 + 0] = (1.f / denom) * alphas[i0] * (1.f / (float)RANK);
        g_w[t * 2 + 1] = (e1 / denom) * alphas[i1] * (1.f / (float)RANK);
    }
}

// ---------------------------------------------------------------------------
// Kernel 3 (s0): mid GEMM with fused weighting epilogue.
//   acc = Xh . Ah^T  (K=2048), then Mw[t, c] = half(w_sel(t, c>>4) * acc)
// tiles 128x64, grid (4,64)=256 CTAs, 128 thr, 4 warps (2x2) of 64x32,
// 6-stage cp.async, 2 CTAs/SM.
// ---------------------------------------------------------------------------
#define MBM 128
#define MBN 64
#define BK 32
#define MID_NSTAGE 6
#define MID_STAGE_BYTES ((MBM + MBN) * 64)       // 12288
#define MID_SMEM (MID_NSTAGE * MID_STAGE_BYTES + 1024)

__global__ void __launch_bounds__(128, 2)
gemm_mid_kernel(const __half* __restrict__ Aop, const __half* __restrict__ Bop) {
    constexpr int KITERS = D_IN / BK;   // 64
    extern __shared__ char dsm[];
    const uint32_t sbase = (smem_u32(dsm) + 1023) & ~1023u;

    const int tid = threadIdx.x;
    const int wid = tid >> 5;
    const int lane = tid & 31;
    const int bm = blockIdx.y * MBM;
    const int bnr = blockIdx.x * MBN;
    const int wm = (wid & 1) * 64;
    const int wn = (wid >> 1) * 32;

    const int lrA = (lane & 7) | (((lane >> 3) & 1) << 3);
    const int ksA = (lane >> 4) & 1;
    const int lrB = (lane & 7) | (((lane >> 4) & 1) << 3);
    const int ksB = (lane >> 3) & 1;

    float acc[4][4][4];
#pragma unroll
    for (int i = 0; i < 4; i++)
#pragma unroll
        for (int j = 0; j < 4; j++)
#pragma unroll
            for (int q = 0; q < 4; q++) acc[i][j][q] = 0.f;

#define MID_ISSUE(stg, ko_)                                                    \
    do {                                                                       \
        const int kk_ = (ko_) * BK;                                            \
        const uint32_t sb_ = sbase + (stg) * MID_STAGE_BYTES;                  \
        _Pragma("unroll")                                                      \
        for (int i_ = 0; i_ < 6; i_++) {                                       \
            int c_ = tid + i_ * 128;   /* [0,768) */                           \
            if (c_ < 512) {                                                    \
                int row_ = c_ >> 2, cc_ = c_ & 3;                              \
                cp16(sb_ + swz_off(row_, cc_),                                 \
                     Aop + (size_t)(bm + row_) * D_IN + kk_ + cc_ * 8);        \
            } else {                                                           \
                int c2_ = c_ - 512;                                            \
                int row_ = c2_ >> 2, cc_ = c2_ & 3;                            \
                cp16(sb_ + 8192 + swz_off(row_, cc_),                          \
                     Bop + (size_t)(bnr + row_) * D_IN + kk_ + cc_ * 8);       \
            }                                                                  \
        }                                                                      \
    } while (0)

#pragma unroll
    for (int s = 0; s < MID_NSTAGE - 1; s++) {
        MID_ISSUE(s, s);
        asm volatile("cp.async.commit_group;" ::: "memory");
    }

    for (int ko = 0; ko < KITERS; ko++) {
        asm volatile("cp.async.wait_group %0;" :: "n"(MID_NSTAGE - 2) : "memory");
        __syncthreads();

        if (ko + MID_NSTAGE - 1 < KITERS)
            MID_ISSUE((ko + MID_NSTAGE - 1) % MID_NSTAGE, ko + MID_NSTAGE - 1);
        asm volatile("cp.async.commit_group;" ::: "memory");

        const uint32_t sb = sbase + (ko % MID_NSTAGE) * MID_STAGE_BYTES;
#pragma unroll
        for (int k16 = 0; k16 < BK; k16 += 16) {
            uint32_t axh[4][4], bwh[2][4];
            const int chA = (k16 >> 3) + ksA;
            const int chB = (k16 >> 3) + ksB;
#pragma unroll
            for (int mt = 0; mt < 4; mt++) {
                int row = wm + mt * 16 + lrA;
                ldsm_x4(axh[mt], sb + swz_off(row, chA));
            }
#pragma unroll
            for (int nt2 = 0; nt2 < 2; nt2++) {
                int row = wn + nt2 * 16 + lrB;
                ldsm_x4(bwh[nt2], sb + 8192 + swz_off(row, chB));
            }
#pragma unroll
            for (int mt = 0; mt < 4; mt++) {
#pragma unroll
                for (int nt = 0; nt < 4; nt++) {
                    uint32_t* bh = &bwh[nt >> 1][(nt & 1) * 2];
                    MMA16816(acc[mt][nt], axh[mt], bh[0], bh[1]);
                }
            }
        }
    }

    // epilogue: apply routing weights, write fp16 Mw directly
#pragma unroll
    for (int mt = 0; mt < 4; mt++) {
        int row0 = bm + wm + mt * 16 + (lane >> 2);
#pragma unroll
        for (int rr = 0; rr < 2; rr++) {
            int t = row0 + rr * 8;
            int e0 = g_idx[t * 2 + 0];
            int e1 = g_idx[t * 2 + 1];
            float w0 = g_w[t * 2 + 0];
            float w1 = g_w[t * 2 + 1];
#pragma unroll
            for (int nt = 0; nt < 4; nt++) {
                int col = bnr + wn + nt * 8 + (lane & 3) * 2;
                int ec = col >> 4;   // col, col+1 share the expert block
                float wsel = (ec == e0) ? w0 : (ec == e1) ? w1 : 0.f;
                float a0 = acc[mt][nt][rr * 2 + 0];
                float a1 = acc[mt][nt][rr * 2 + 1];
                *(__half2*)(g_Mw + (size_t)t * KLORA + col) =
                    __half2(__float2half(wsel * a0), __float2half(wsel * a1));
            }
        }
    }
#undef MID_ISSUE
}

// ---------------------------------------------------------------------------
// Kernel 4 (s0): main GEMM. 128x128 tile, 4 warps (128 thr) of 64x64, BK=32,
// 6-stage, 2 CTAs/SM. Two K phases (W then fused LoRA) + write-only epilogue.
// ---------------------------------------------------------------------------
#define GBM 128
#define GBN 128
#define GNSTAGE 6
#define GSTAGE_BYTES (2 * 128 * 64)              // 16KB
#define MAIN_SMEM (GNSTAGE * GSTAGE_BYTES + 1024)

__global__ void __launch_bounds__(128, 2)
gemm_main_kernel(float* __restrict__ out, const float* __restrict__ bias) {
    extern __shared__ char dsm[];
    const uint32_t sbase = (smem_u32(dsm) + 1023) & ~1023u;

    const int tid = threadIdx.x;
    const int wid = tid >> 5;
    const int lane = tid & 31;
    const int bm = blockIdx.y * GBM;
    const int bn = blockIdx.x * GBN;
    const int wm = (wid & 1) * 64;
    const int wn = (wid >> 1) * 64;

    const int lrA = (lane & 7) | (((lane >> 3) & 1) << 3);
    const int ksA = (lane >> 4) & 1;
    const int lrB = (lane & 7) | (((lane >> 4) & 1) << 3);
    const int ksB = (lane >> 3) & 1;

    float acc[4][8][4];
#pragma unroll
    for (int i = 0; i < 4; i++)
#pragma unroll
        for (int j = 0; j < 8; j++)
#pragma unroll
            for (int q = 0; q < 4; q++) acc[i][j][q] = 0.f;

#define MAIN_ISSUE(stg, ko_, AP, BP, KL)                                       \
    do {                                                                       \
        const int kk_ = (ko_) * BK;                                            \
        const uint32_t sb_ = sbase + (stg) * GSTAGE_BYTES;                     \
        _Pragma("unroll")                                                      \
        for (int i_ = 0; i_ < 8; i_++) {                                       \
            int c_ = tid + i_ * 128;   /* [0,1024) */                          \
            int tile_ = c_ >> 9;                                               \
            int row_ = (c_ >> 2) & 127;                                        \
            int cc_ = c_ & 3;                                                  \
            const __half* srcb_ = (tile_ == 0)                                 \
                ? ((AP) + (size_t)(bm + row_) * (KL))                          \
                : ((BP) + (size_t)(bn + row_) * (KL));                         \
            cp16(sb_ + tile_ * 8192 + swz_off(row_, cc_),                      \
                 srcb_ + kk_ + cc_ * 8);                                       \
        }                                                                      \
    } while (0)

#define MAIN_COMPUTE(sb)                                                       \
    do {                                                                       \
        _Pragma("unroll")                                                      \
        for (int k16 = 0; k16 < BK; k16 += 16) {                               \
            uint32_t axh[4][4], bwh[4][4];                                     \
            const int chA = (k16 >> 3) + ksA;                                  \
            const int chB = (k16 >> 3) + ksB;                                  \
            _Pragma("unroll")                                                  \
            for (int mt = 0; mt < 4; mt++) {                                   \
                int row = wm + mt * 16 + lrA;                                  \
                ldsm_x4(axh[mt], (sb) + swz_off(row, chA));                    \
            }                                                                  \
            _Pragma("unroll")                                                  \
            for (int nt2 = 0; nt2 < 4; nt2++) {                                \
                int row = wn + nt2 * 16 + lrB;                                 \
                ldsm_x4(bwh[nt2], (sb) + 8192 + swz_off(row, chB));            \
            }                                                                  \
            _Pragma("unroll")                                                  \
            for (int mt = 0; mt < 4; mt++) {                                   \
                _Pragma("unroll")                                              \
                for (int nt = 0; nt < 8; nt++) {                               \
                    uint32_t* bh = &bwh[nt >> 1][(nt & 1) * 2];                \
                    MMA16816(acc[mt][nt], axh[mt], bh[0], bh[1]);              \
                }                                                              \
            }                                                                  \
        }                                                                      \
    } while (0)

    // ---- phase 1: K = 2048 over Xh / Wh ----
    {
        constexpr int KIT = D_IN / BK;   // 64
#pragma unroll
        for (int s = 0; s < GNSTAGE - 1; s++) {
            MAIN_ISSUE(s, s, g_Xh, g_Wh, D_IN);
            asm volatile("cp.async.commit_group;" ::: "memory");
        }
        for (int ko = 0; ko < KIT; ko++) {
            asm volatile("cp.async.wait_group %0;" :: "n"(GNSTAGE - 2) : "memory");
            __syncthreads();
            if (ko + GNSTAGE - 1 < KIT)
                MAIN_ISSUE((ko + GNSTAGE - 1) % GNSTAGE, ko + GNSTAGE - 1,
                           g_Xh, g_Wh, D_IN);
            asm volatile("cp.async.commit_group;" ::: "memory");
            MAIN_COMPUTE(sbase + (ko % GNSTAGE) * GSTAGE_BYTES);
        }
    }
    asm volatile("cp.async.wait_group 0;" ::: "memory");
    __syncthreads();

    // ---- phase 2: K = 256 over Mw / Bh (fused LoRA combine) ----
    {
        constexpr int KIT = KLORA / BK;  // 8
#pragma unroll
        for (int s = 0; s < GNSTAGE - 1; s++) {
            if (s < KIT) MAIN_ISSUE(s, s, g_Mw, g_Bh, KLORA);
            asm volatile("cp.async.commit_group;" ::: "memory");
        }
        for (int ko = 0; ko < KIT; ko++) {
            asm volatile("cp.async.wait_group %0;" :: "n"(GNSTAGE - 2) : "memory");
            __syncthreads();
            if (ko + GNSTAGE - 1 < KIT)
                MAIN_ISSUE((ko + GNSTAGE - 1) % GNSTAGE, ko + GNSTAGE - 1,
                           g_Mw, g_Bh, KLORA);
            asm volatile("cp.async.commit_group;" ::: "memory");
            MAIN_COMPUTE(sbase + (ko % GNSTAGE) * GSTAGE_BYTES);
        }
    }

    // epilogue: out = acc + bias (write-only)
#pragma unroll
    for (int mt = 0; mt < 4; mt++) {
#pragma unroll
        for (int nt = 0; nt < 8; nt++) {
            int row = bm + wm + mt * 16 + (lane >> 2);
            int col = bn + wn + nt * 8 + (lane & 3) * 2;
            float bx = bias[col], by = bias[col + 1];
            *(float2*)(out + (size_t)row * D_OUT + col) =
                make_float2(acc[mt][nt][0] + bx, acc[mt][nt][1] + by);
            *(float2*)(out + (size_t)(row + 8) * D_OUT + col) =
                make_float2(acc[mt][nt][2] + bx, acc[mt][nt][3] + by);
        }
    }
#undef MAIN_ISSUE
#undef MAIN_COMPUTE
}

// ---------------------------------------------------------------------------
// Launch: 4 kernels total. prep on s1 (overlaps convx); rest on s0.
// Issue order: prep(1), convx(2), mid(3), main(4) -> ncu profiles main.
// ---------------------------------------------------------------------------
extern "C" void kernel_launch(void* const* d_in, const int* in_sizes, int n_in,
                              void* d_out, int out_size) {
    const float* x  = (const float*)d_in[0];
    const float* Wm = (const float*)d_in[1];
    const float* bb = (const float*)d_in[2];
    const float* A  = (const float*)d_in[3];
    const float* B  = (const float*)d_in[4];
    const float* gv = (const float*)d_in[5];
    const float* al = (const float*)d_in[6];
    float* out = (float*)d_out;

    int T = in_sizes[0] / D_IN;   // 8192

    static bool init_done = false;
    static __half *xh, *ah;
    static cudaStream_t s1;
    static cudaEvent_t ev_fork, ev_prep;
    if (!init_done) {
        cudaFuncSetAttribute(gemm_mid_kernel,
                             cudaFuncAttributeMaxDynamicSharedMemorySize,
                             MID_SMEM);
        cudaFuncSetAttribute(gemm_main_kernel,
                             cudaFuncAttributeMaxDynamicSharedMemorySize,
                             MAIN_SMEM);
        cudaFuncSetAttribute(convx_kernel,
                             cudaFuncAttributeMaxDynamicSharedMemorySize,
                             CONVX_SMEM);
        cudaGetSymbolAddress((void**)&xh, g_Xh);
        cudaGetSymbolAddress((void**)&ah, g_Ah);
        cudaStreamCreateWithFlags(&s1, cudaStreamNonBlocking);
        cudaEventCreateWithFlags(&ev_fork, cudaEventDisableTiming);
        cudaEventCreateWithFlags(&ev_prep, cudaEventDisableTiming);
        init_done = true;
    }

    cudaStream_t s0 = 0;   // capture stream

    // fork s1
    cudaEventRecord(ev_fork, s0);
    cudaStreamWaitEvent(s1, ev_fork, 0);

    // 1 (s1): weight prep (Wh, Ah, Bh)
    prep_kernel<<<PREP_BLOCKS, 256, 0, s1>>>(Wm, A, B);
    cudaEventRecord(ev_prep, s1);

    // 2 (s0): convx (Xh + routing: dots, gnorm, top-2, softmax)
    convx_kernel<<<T / CONVX_TOKENS, 512, CONVX_SMEM, s0>>>(x, gv, al);

    // join: mid needs Ah
    cudaStreamWaitEvent(s0, ev_prep, 0);

    // 3 (s0): mid GEMM + weighted fp16 epilogue -> Mw
    gemm_mid_kernel<<<dim3(KLORA / MBN, T / MBM), 128, MID_SMEM, s0>>>(xh, ah);

    // 4 (s0): main GEMM (out = Xh.Wh^T + Mw.Bh^T + bias)
    gemm_main_kernel<<<dim3(D_OUT / GBN, T / GBM), 128, MAIN_SMEM, s0>>>(out, bb);
}

// round 16
// speedup vs baseline: 1.0985x; 1.0985x over previous
#include <cuda_runtime.h>
#include <cuda_fp16.h>
#include <math.h>
#include <stdint.h>

// ---------------------------------------------------------------------------
// Shapes (fixed): x [4,2048,2048] -> T=8192, d=2048 ; base_W [2048,2048];
// base_b [2048]; A [16,16,2048]; B [16,2048,16]; gate_v [16,2048];
// alphas[16]; top_k=2
// ---------------------------------------------------------------------------

#define D_IN   2048
#define D_OUT  2048
#define N_EXP  16
#define RANK   16
#define T_MAX  8192
#define EPSV   1e-6f
#define KLORA  (N_EXP * RANK)           // 256

// Scratch (static device memory -- no allocation)
__device__ float g_xnorm[T_MAX];
__device__ float g_dots[T_MAX * N_EXP];
__device__ int   g_idx[T_MAX * 2];
__device__ float g_w[T_MAX * 2];
__device__ float g_midd[(size_t)T_MAX * KLORA];

// fp16 operands
__device__ __half g_Xh[(size_t)T_MAX * D_IN];
__device__ __half g_Wh[(size_t)D_OUT * D_IN];
__device__ __half g_Ah[(size_t)KLORA * D_IN];
__device__ __half g_Mw[(size_t)T_MAX * KLORA];
__device__ __half g_Bh[(size_t)D_OUT * KLORA];

// ---------------------------------------------------------------------------
// PTX helpers
// ---------------------------------------------------------------------------
__device__ __forceinline__ uint32_t smem_u32(const void* p) {
    uint32_t a;
    asm("{ .reg .u64 t; cvta.to.shared.u64 t, %1; cvt.u32.u64 %0, t; }"
        : "=r"(a) : "l"(p));
    return a;
}
__device__ __forceinline__ void cp16(uint32_t dst, const void* src) {
    asm volatile("cp.async.cg.shared.global [%0], [%1], 16;" :: "r"(dst), "l"(src));
}
__device__ __forceinline__ void ldsm_x4(uint32_t* r, uint32_t addr) {
    asm volatile("ldmatrix.sync.aligned.m8n8.x4.shared.b16 {%0,%1,%2,%3}, [%4];"
                 : "=r"(r[0]), "=r"(r[1]), "=r"(r[2]), "=r"(r[3]) : "r"(addr));
}
#define MMA16816(cd, af, b0, b1)                                              \
    asm volatile("mma.sync.aligned.m16n8k16.row.col.f32.f16.f16.f32 "        \
                 "{%0,%1,%2,%3}, {%4,%5,%6,%7}, {%8,%9}, {%0,%1,%2,%3};"      \
                 : "+f"((cd)[0]), "+f"((cd)[1]), "+f"((cd)[2]), "+f"((cd)[3]) \
                 : "r"((af)[0]), "r"((af)[1]), "r"((af)[2]), "r"((af)[3]),    \
                   "r"(b0), "r"(b1))

// 64B-row swizzle (BK=32 tiles, mid GEMM)
__device__ __forceinline__ uint32_t swz_off(int row, int chunk) {
    int s = (row & 3) ^ ((row >> 2) & 1);
    return (uint32_t)(row * 64 + ((chunk ^ s) << 4));
}
// 128B-row swizzle (BK=64 tiles, main GEMM): 8 chunks of 16B per row
__device__ __forceinline__ uint32_t swz128(int row, int chunk) {
    return (uint32_t)(row * 128 + ((chunk ^ (row & 7)) << 4));
}

// ---------------------------------------------------------------------------
// Kernel: X fp32 -> fp16 + per-token norm + routing dots (fp32 exact path).
// ---------------------------------------------------------------------------
#define CONVX_TOKENS 16
#define CONVX_SMEM (CONVX_TOKENS * D_IN * 4)   // 128KB

__global__ void __launch_bounds__(512)
convx_kernel(const float* __restrict__ x, const float* __restrict__ gv) {
    extern __shared__ float xs[];
    const int t0 = blockIdx.x * CONVX_TOKENS;
    const int w = threadIdx.x >> 5;
    const int l = threadIdx.x & 31;

    {
        const float4* xr = (const float4*)(x + (size_t)(t0 + w) * D_IN);
        float4* xsr = (float4*)(xs + (size_t)w * D_IN);
        __half2* hp = (__half2*)(g_Xh + (size_t)(t0 + w) * D_IN);
        float xx = 0.f;
#pragma unroll
        for (int i = 0; i < 16; i++) {
            int j = l + 32 * i;
            float4 v = xr[j];
            xsr[j] = v;
            xx += v.x * v.x + v.y * v.y + v.z * v.z + v.w * v.w;
            hp[j * 2 + 0] = __half2(__float2half(v.x), __float2half(v.y));
            hp[j * 2 + 1] = __half2(__float2half(v.z), __float2half(v.w));
        }
#pragma unroll
        for (int off = 16; off > 0; off >>= 1)
            xx += __shfl_down_sync(0xFFFFFFFFu, xx, off);
        if (l == 0) g_xnorm[t0 + w] = sqrtf(xx) + EPSV;
    }
    __syncthreads();

    float gvr[64];
    {
        const float* gvrow = gv + (size_t)w * D_IN;
#pragma unroll
        for (int i = 0; i < 64; i++) gvr[i] = gvrow[l + 32 * i];
    }
#pragma unroll 1
    for (int t = 0; t < CONVX_TOKENS; t++) {
        const float* xt = xs + (size_t)t * D_IN;
        float s = 0.f;
#pragma unroll
        for (int i = 0; i < 64; i++) s += xt[l + 32 * i] * gvr[i];
#pragma unroll
        for (int off = 16; off > 0; off >>= 1)
            s += __shfl_down_sync(0xFFFFFFFFu, s, off);
        if (l == 0) g_dots[(size_t)(t0 + t) * N_EXP + w] = s;
    }
}

// ---------------------------------------------------------------------------
// Kernel: generic fp32 -> fp16 conversion
// ---------------------------------------------------------------------------
__global__ void convh_kernel(const float* __restrict__ src,
                             __half* __restrict__ dst, int n4) {
    int i = blockIdx.x * blockDim.x + threadIdx.x;
    if (i >= n4) return;
    float4 v = ((const float4*)src)[i];
    __half2* dp = (__half2*)dst;
    dp[2 * i + 0] = __half2(__float2half(v.x), __float2half(v.y));
    dp[2 * i + 1] = __half2(__float2half(v.z), __float2half(v.w));
}

// ---------------------------------------------------------------------------
// Kernel: transpose B [E, d_out, r] -> Bh [d_out, E*r] fp16
// ---------------------------------------------------------------------------
__global__ void __launch_bounds__(256)
convB_kernel(const float* __restrict__ B) {
    int gidx = blockIdx.x * 256 + threadIdx.x;
    int o = gidx >> 4;
    int e = gidx & 15;
    const float4* src = (const float4*)(B + ((size_t)e * D_OUT + o) * RANK);
    __half2 buf[8];
#pragma unroll
    for (int q = 0; q < 4; q++) {
        float4 v = src[q];
        buf[q * 2 + 0] = __half2(__float2half(v.x), __float2half(v.y));
        buf[q * 2 + 1] = __half2(__float2half(v.z), __float2half(v.w));
    }
    uint4* dst = (uint4*)(g_Bh + (size_t)o * KLORA + e * RANK);
    dst[0] = ((uint4*)buf)[0];
    dst[1] = ((uint4*)buf)[1];
}

// ---------------------------------------------------------------------------
// Kernel: gate norms + top-2 + softmax.
// ---------------------------------------------------------------------------
__global__ void __launch_bounds__(256)
topk_kernel(const float* __restrict__ gv, const float* __restrict__ alphas) {
    __shared__ float gn[N_EXP];
    const int w = threadIdx.x >> 5;
    const int l = threadIdx.x & 31;

#pragma unroll
    for (int p = 0; p < 2; p++) {
        int e = w + 8 * p;
        const float4* gr = (const float4*)(gv + (size_t)e * D_IN);
        float s = 0.f;
#pragma unroll
        for (int i = 0; i < 16; i++) {
            float4 v = gr[l + 32 * i];
            s += v.x * v.x + v.y * v.y + v.z * v.z + v.w * v.w;
        }
#pragma unroll
        for (int off = 16; off > 0; off >>= 1)
            s += __shfl_down_sync(0xFFFFFFFFu, s, off);
        if (l == 0) gn[e] = sqrtf(s) + EPSV;
    }
    __syncthreads();

    int t = blockIdx.x * 256 + threadIdx.x;
    if (t >= T_MAX) return;

    float inv = 1.f / (g_xnorm[t] * sqrtf((float)D_IN));
    float sc[N_EXP];
#pragma unroll
    for (int e = 0; e < N_EXP; e++)
        sc[e] = g_dots[t * N_EXP + e] * inv / gn[e];

    int i0 = 0;
#pragma unroll
    for (int e = 1; e < N_EXP; e++) if (sc[e] > sc[i0]) i0 = e;
    int i1 = (i0 == 0) ? 1 : 0;
#pragma unroll
    for (int e = 0; e < N_EXP; e++)
        if (e != i0 && sc[e] > sc[i1]) i1 = e;

    float e1 = expf(sc[i1] - sc[i0]);
    float denom = 1.f + e1;
    g_idx[t * 2 + 0] = i0;
    g_idx[t * 2 + 1] = i1;
    g_w[t * 2 + 0] = (1.f / denom) * alphas[i0] * (1.f / (float)RANK);
    g_w[t * 2 + 1] = (e1 / denom) * alphas[i1] * (1.f / (float)RANK);
}

// ---------------------------------------------------------------------------
// Kernel: midw[t, e*16+r] = w_{t,k} * midd[t, e*16+r] (selected), 0 else.
// ---------------------------------------------------------------------------
__global__ void __launch_bounds__(256)
midw_kernel() {
    const int t = blockIdx.x * 32 + (threadIdx.x >> 3);
    const int j = threadIdx.x & 7;
    const int e0 = g_idx[t * 2 + 0];
    const int e1 = g_idx[t * 2 + 1];
    const float w0 = g_w[t * 2 + 0];
    const float w1 = g_w[t * 2 + 1];
    const float* mrow = g_midd + (size_t)t * KLORA;

    __half2 buf[16];
    const int p0 = j * 32;
#pragma unroll
    for (int q = 0; q < 16; q++) {
        int p = p0 + q * 2;
        int ea = p >> 4;
        float va = 0.f, vb = 0.f;
        if (ea == e0)      { va = w0 * mrow[p]; vb = w0 * mrow[p + 1]; }
        else if (ea == e1) { va = w1 * mrow[p]; vb = w1 * mrow[p + 1]; }
        buf[q] = __half2(__float2half(va), __float2half(vb));
    }
    uint4* dst = (uint4*)(g_Mw + (size_t)t * KLORA + p0);
#pragma unroll
    for (int q = 0; q < 4; q++) dst[q] = ((uint4*)buf)[q];
}

// ---------------------------------------------------------------------------
// mid GEMM: midd = Xh . Ah^T  (K=2048), tiles 128x64, grid (4,64)=256 CTAs.
// 128 thr, 4 warps (2x2) of 64x32, BK=32, 6-stage cp.async, 2 CTAs/SM.
// ---------------------------------------------------------------------------
#define MBM 128
#define MBN 64
#define BK 32
#define MID_NSTAGE 6
#define MID_STAGE_BYTES ((MBM + MBN) * 64)       // 12288
#define MID_SMEM (MID_NSTAGE * MID_STAGE_BYTES + 1024)

__global__ void __launch_bounds__(128, 2)
gemm_mid_kernel(const __half* __restrict__ Aop, const __half* __restrict__ Bop,
                float* __restrict__ midd) {
    constexpr int KITERS = D_IN / BK;   // 64
    extern __shared__ char dsm[];
    const uint32_t sbase = (smem_u32(dsm) + 1023) & ~1023u;

    const int tid = threadIdx.x;
    const int wid = tid >> 5;
    const int lane = tid & 31;
    const int bm = blockIdx.y * MBM;
    const int bnr = blockIdx.x * MBN;
    const int wm = (wid & 1) * 64;
    const int wn = (wid >> 1) * 32;

    const int lrA = (lane & 7) | (((lane >> 3) & 1) << 3);
    const int ksA = (lane >> 4) & 1;
    const int lrB = (lane & 7) | (((lane >> 4) & 1) << 3);
    const int ksB = (lane >> 3) & 1;

    float acc[4][4][4];
#pragma unroll
    for (int i = 0; i < 4; i++)
#pragma unroll
        for (int j = 0; j < 4; j++)
#pragma unroll
            for (int q = 0; q < 4; q++) acc[i][j][q] = 0.f;

#define MID_ISSUE(stg, ko_)                                                    \
    do {                                                                       \
        const int kk_ = (ko_) * BK;                                            \
        const uint32_t sb_ = sbase + (stg) * MID_STAGE_BYTES;                  \
        _Pragma("unroll")                                                      \
        for (int i_ = 0; i_ < 6; i_++) {                                       \
            int c_ = tid + i_ * 128;   /* [0,768) */                           \
            if (c_ < 512) {                                                    \
                int row_ = c_ >> 2, cc_ = c_ & 3;                              \
                cp16(sb_ + swz_off(row_, cc_),                                 \
                     Aop + (size_t)(bm + row_) * D_IN + kk_ + cc_ * 8);        \
            } else {                                                           \
                int c2_ = c_ - 512;                                            \
                int row_ = c2_ >> 2, cc_ = c2_ & 3;                            \
                cp16(sb_ + 8192 + swz_off(row_, cc_),                          \
                     Bop + (size_t)(bnr + row_) * D_IN + kk_ + cc_ * 8);       \
            }                                                                  \
        }                                                                      \
    } while (0)

#pragma unroll
    for (int s = 0; s < MID_NSTAGE - 1; s++) {
        MID_ISSUE(s, s);
        asm volatile("cp.async.commit_group;" ::: "memory");
    }

    for (int ko = 0; ko < KITERS; ko++) {
        asm volatile("cp.async.wait_group %0;" :: "n"(MID_NSTAGE - 2) : "memory");
        __syncthreads();

        if (ko + MID_NSTAGE - 1 < KITERS)
            MID_ISSUE((ko + MID_NSTAGE - 1) % MID_NSTAGE, ko + MID_NSTAGE - 1);
        asm volatile("cp.async.commit_group;" ::: "memory");

        const uint32_t sb = sbase + (ko % MID_NSTAGE) * MID_STAGE_BYTES;
#pragma unroll
        for (int k16 = 0; k16 < BK; k16 += 16) {
            uint32_t axh[4][4], bwh[2][4];
            const int chA = (k16 >> 3) + ksA;
            const int chB = (k16 >> 3) + ksB;
#pragma unroll
            for (int mt = 0; mt < 4; mt++) {
                int row = wm + mt * 16 + lrA;
                ldsm_x4(axh[mt], sb + swz_off(row, chA));
            }
#pragma unroll
            for (int nt2 = 0; nt2 < 2; nt2++) {
                int row = wn + nt2 * 16 + lrB;
                ldsm_x4(bwh[nt2], sb + 8192 + swz_off(row, chB));
            }
#pragma unroll
            for (int mt = 0; mt < 4; mt++) {
#pragma unroll
                for (int nt = 0; nt < 4; nt++) {
                    uint32_t* bh = &bwh[nt >> 1][(nt & 1) * 2];
                    MMA16816(acc[mt][nt], axh[mt], bh[0], bh[1]);
                }
            }
        }
    }

#pragma unroll
    for (int mt = 0; mt < 4; mt++) {
#pragma unroll
        for (int nt = 0; nt < 4; nt++) {
            int row = bm + wm + mt * 16 + (lane >> 2);
            int col = bnr + wn + nt * 8 + (lane & 3) * 2;
            *(float2*)(midd + (size_t)row * KLORA + col) =
                make_float2(acc[mt][nt][0], acc[mt][nt][1]);
            *(float2*)(midd + (size_t)(row + 8) * KLORA + col) =
                make_float2(acc[mt][nt][2], acc[mt][nt][3]);
        }
    }
#undef MID_ISSUE
}

// ---------------------------------------------------------------------------
// Main GEMM: 128x128 tile, 4 warps (128 thr) of 64x64, BK=64, 3-stage,
// 2 CTAs/SM (3 x 32KB x 2 = 192KB smem). Halves barrier count vs BK=32.
// Two K phases (W then fused LoRA) + write-only epilogue.
// ---------------------------------------------------------------------------
#define GBM 128
#define GBN 128
#define GBK 64
#define GNSTAGE 3
#define GSTAGE_BYTES (2 * 128 * 128)             // 32KB
#define MAIN_SMEM (GNSTAGE * GSTAGE_BYTES + 1024)

__global__ void __launch_bounds__(128, 2)
gemm_main_kernel(float* __restrict__ out, const float* __restrict__ bias) {
    extern __shared__ char dsm[];
    const uint32_t sbase = (smem_u32(dsm) + 1023) & ~1023u;

    const int tid = threadIdx.x;
    const int wid = tid >> 5;
    const int lane = tid & 31;
    const int bm = blockIdx.y * GBM;
    const int bn = blockIdx.x * GBN;
    const int wm = (wid & 1) * 64;
    const int wn = (wid >> 1) * 64;

    const int lrA = (lane & 7) | (((lane >> 3) & 1) << 3);
    const int ksA = (lane >> 4) & 1;
    const int lrB = (lane & 7) | (((lane >> 4) & 1) << 3);
    const int ksB = (lane >> 3) & 1;

    float acc[4][8][4];
#pragma unroll
    for (int i = 0; i < 4; i++)
#pragma unroll
        for (int j = 0; j < 8; j++)
#pragma unroll
            for (int q = 0; q < 4; q++) acc[i][j][q] = 0.f;

    // per stage: 2 tiles x 128 rows x 8 chunks(16B) = 2048 chunks; 16/thread
#define MAIN_ISSUE(stg, ko_, AP, BP, KL)                                       \
    do {                                                                       \
        const int kk_ = (ko_) * GBK;                                           \
        const uint32_t sb_ = sbase + (stg) * GSTAGE_BYTES;                     \
        _Pragma("unroll")                                                      \
        for (int i_ = 0; i_ < 16; i_++) {                                      \
            int c_ = tid + i_ * 128;   /* [0,2048) */                          \
            int tile_ = c_ >> 10;                                              \
            int row_ = (c_ >> 3) & 127;                                        \
            int cc_ = c_ & 7;                                                  \
            const __half* srcb_ = (tile_ == 0)                                 \
                ? ((AP) + (size_t)(bm + row_) * (KL))                          \
                : ((BP) + (size_t)(bn + row_) * (KL));                         \
            cp16(sb_ + tile_ * 16384 + swz128(row_, cc_),                      \
                 srcb_ + kk_ + cc_ * 8);                                       \
        }                                                                      \
    } while (0)

#define MAIN_COMPUTE(sb)                                                       \
    do {                                                                       \
        _Pragma("unroll")                                                      \
        for (int k16 = 0; k16 < GBK; k16 += 16) {                              \
            uint32_t axh[4][4], bwh[4][4];                                     \
            const int chA = (k16 >> 3) + ksA;                                  \
            const int chB = (k16 >> 3) + ksB;                                  \
            _Pragma("unroll")                                                  \
            for (int mt = 0; mt < 4; mt++) {                                   \
                int row = wm + mt * 16 + lrA;                                  \
                ldsm_x4(axh[mt], (sb) + swz128(row, chA));                     \
            }                                                                  \
            _Pragma("unroll")                                                  \
            for (int nt2 = 0; nt2 < 4; nt2++) {                                \
                int row = wn + nt2 * 16 + lrB;                                 \
                ldsm_x4(bwh[nt2], (sb) + 16384 + swz128(row, chB));            \
            }                                                                  \
            _Pragma("unroll")                                                  \
            for (int mt = 0; mt < 4; mt++) {                                   \
                _Pragma("unroll")                                              \
                for (int nt = 0; nt < 8; nt++) {                               \
                    uint32_t* bh = &bwh[nt >> 1][(nt & 1) * 2];                \
                    MMA16816(acc[mt][nt], axh[mt], bh[0], bh[1]);              \
                }                                                              \
            }                                                                  \
        }                                                                      \
    } while (0)

    // ---- phase 1: K = 2048 over Xh / Wh (32 iters) ----
    {
        constexpr int KIT = D_IN / GBK;   // 32
#pragma unroll
        for (int s = 0; s < GNSTAGE - 1; s++) {
            MAIN_ISSUE(s, s, g_Xh, g_Wh, D_IN);
            asm volatile("cp.async.commit_group;" ::: "memory");
        }
        for (int ko = 0; ko < KIT; ko++) {
            asm volatile("cp.async.wait_group %0;" :: "n"(GNSTAGE - 2) : "memory");
            __syncthreads();
            if (ko + GNSTAGE - 1 < KIT)
                MAIN_ISSUE((ko + GNSTAGE - 1) % GNSTAGE, ko + GNSTAGE - 1,
                           g_Xh, g_Wh, D_IN);
            asm volatile("cp.async.commit_group;" ::: "memory");
            MAIN_COMPUTE(sbase + (ko % GNSTAGE) * GSTAGE_BYTES);
        }
    }
    asm volatile("cp.async.wait_group 0;" ::: "memory");
    __syncthreads();

    // ---- phase 2: K = 256 over Mw / Bh (4 iters) ----
    {
        constexpr int KIT = KLORA / GBK;  // 4
#pragma unroll
        for (int s = 0; s < GNSTAGE - 1; s++) {
            if (s < KIT) MAIN_ISSUE(s, s, g_Mw, g_Bh, KLORA);
            asm volatile("cp.async.commit_group;" ::: "memory");
        }
        for (int ko = 0; ko < KIT; ko++) {
            asm volatile("cp.async.wait_group %0;" :: "n"(GNSTAGE - 2) : "memory");
            __syncthreads();
            if (ko + GNSTAGE - 1 < KIT)
                MAIN_ISSUE((ko + GNSTAGE - 1) % GNSTAGE, ko + GNSTAGE - 1,
                           g_Mw, g_Bh, KLORA);
            asm volatile("cp.async.commit_group;" ::: "memory");
            MAIN_COMPUTE(sbase + (ko % GNSTAGE) * GSTAGE_BYTES);
        }
    }

    // epilogue: out = acc + bias (write-only)
#pragma unroll
    for (int mt = 0; mt < 4; mt++) {
#pragma unroll
        for (int nt = 0; nt < 8; nt++) {
            int row = bm + wm + mt * 16 + (lane >> 2);
            int col = bn + wn + nt * 8 + (lane & 3) * 2;
            float bx = bias[col], by = bias[col + 1];
            *(float2*)(out + (size_t)row * D_OUT + col) =
                make_float2(acc[mt][nt][0] + bx, acc[mt][nt][1] + by);
            *(float2*)(out + (size_t)(row + 8) * D_OUT + col) =
                make_float2(acc[mt][nt][2] + bx, acc[mt][nt][3] + by);
        }
    }
#undef MAIN_ISSUE
#undef MAIN_COMPUTE
}

// ---------------------------------------------------------------------------
// Launch: round-14 proven two-stream DAG.
// ---------------------------------------------------------------------------
extern "C" void kernel_launch(void* const* d_in, const int* in_sizes, int n_in,
                              void* d_out, int out_size) {
    const float* x  = (const float*)d_in[0];
    const float* Wm = (const float*)d_in[1];
    const float* bb = (const float*)d_in[2];
    const float* A  = (const float*)d_in[3];
    const float* B  = (const float*)d_in[4];
    const float* gv = (const float*)d_in[5];
    const float* al = (const float*)d_in[6];
    float* out = (float*)d_out;

    int T = in_sizes[0] / D_IN;   // 8192

    static bool init_done = false;
    static __half *xh, *wh, *ah;
    static float* midd;
    static cudaStream_t s1;
    static cudaEvent_t ev_fork, ev_convx, ev_A, ev_side;
    if (!init_done) {
        cudaFuncSetAttribute(gemm_mid_kernel,
                             cudaFuncAttributeMaxDynamicSharedMemorySize,
                             MID_SMEM);
        cudaFuncSetAttribute(gemm_main_kernel,
                             cudaFuncAttributeMaxDynamicSharedMemorySize,
                             MAIN_SMEM);
        cudaFuncSetAttribute(convx_kernel,
                             cudaFuncAttributeMaxDynamicSharedMemorySize,
                             CONVX_SMEM);
        cudaGetSymbolAddress((void**)&xh, g_Xh);
        cudaGetSymbolAddress((void**)&wh, g_Wh);
        cudaGetSymbolAddress((void**)&ah, g_Ah);
        cudaGetSymbolAddress((void**)&midd, g_midd);
        cudaStreamCreateWithFlags(&s1, cudaStreamNonBlocking);
        cudaEventCreateWithFlags(&ev_fork,  cudaEventDisableTiming);
        cudaEventCreateWithFlags(&ev_convx, cudaEventDisableTiming);
        cudaEventCreateWithFlags(&ev_A,     cudaEventDisableTiming);
        cudaEventCreateWithFlags(&ev_side,  cudaEventDisableTiming);
        init_done = true;
    }

    cudaStream_t s0 = 0;

    cudaEventRecord(ev_fork, s0);
    cudaStreamWaitEvent(s1, ev_fork, 0);

    // s1: weight conversions + routing side work
    convh_kernel<<<(D_OUT * D_IN / 4 + 255) / 256, 256, 0, s1>>>(
        Wm, wh, D_OUT * D_IN / 4);
    convh_kernel<<<(KLORA * D_IN / 4 + 255) / 256, 256, 0, s1>>>(
        A, ah, KLORA * D_IN / 4);
    cudaEventRecord(ev_A, s1);
    convB_kernel<<<D_OUT * N_EXP / 256, 256, 0, s1>>>(B);

    // s0: critical path
    convx_kernel<<<T / CONVX_TOKENS, 512, CONVX_SMEM, s0>>>(x, gv);
    cudaEventRecord(ev_convx, s0);

    cudaStreamWaitEvent(s1, ev_convx, 0);
    topk_kernel<<<(T + 255) / 256, 256, 0, s1>>>(gv, al);
    cudaEventRecord(ev_side, s1);

    cudaStreamWaitEvent(s0, ev_A, 0);
    gemm_mid_kernel<<<dim3(KLORA / MBN, T / MBM), 128, MID_SMEM, s0>>>(
        xh, ah, midd);

    cudaStreamWaitEvent(s0, ev_side, 0);
    midw_kernel<<<T / 32, 256, 0, s0>>>();

    gemm_main_kernel<<<dim3(D_OUT / GBN, T / GBM), 128, MAIN_SMEM, s0>>>(out, bb);
}